// round 8
// baseline (speedup 1.0000x reference)
#include <cuda_runtime.h>

// RelationAwareAttention: B=1, H=8, L=512, D=64
// out = concat(attn_sum[1,8,512,64], p_attn[1,8,512,512]) as float32.
// G=2 query rows per CTA: each k[j]/v[j] L2 read serves 2 rows, halving LTS traffic.

#define L_SEQ 512
#define D_DIM 64
#define H_HEADS 8
#define NTHREADS 256

__global__ __launch_bounds__(NTHREADS)
void rel_attn_kernel(const float* __restrict__ q_g,
                     const float* __restrict__ k_g,
                     const float* __restrict__ v_g,
                     const float* __restrict__ rk_g,
                     const float* __restrict__ rv_g,
                     const int*   __restrict__ mask_g,
                     float* __restrict__ out_attn,
                     float* __restrict__ out_p)
{
    const int ip   = blockIdx.x;        // i-pair index: rows i0 = 2*ip, i0+1
    const int h    = blockIdx.y;        // head
    const int i0   = ip << 1;
    const int tid  = threadIdx.x;
    const int warp = tid >> 5;
    const int lane = tid & 31;
    const int half = lane >> 4;         // which j of the pair this half-warp owns
    const int hl   = lane & 15;         // lane within half-warp

    __shared__ float  s_score[2][L_SEQ];
    __shared__ int    s_mask[2][L_SEQ];
    __shared__ float  s_red[2][4];
    __shared__ float4 s_acc[2][16][16]; // [row][j-group][d-quad]

    const float* q0   = q_g  + ((size_t)h * L_SEQ + i0) * D_DIM;     // q1 = q0 + 64
    const float* krow = k_g  + (size_t)h * L_SEQ * D_DIM;
    const float* rk0  = rk_g + ((size_t)h * L_SEQ + i0) * L_SEQ * D_DIM;  // rk1 = rk0 + L*D
    const int*   m0   = mask_g + (size_t)i0 * L_SEQ;                 // mask broadcast over h

    // Preload both mask rows (coalesced).
    s_mask[0][tid]       = m0[tid];
    s_mask[0][tid + 256] = m0[tid + 256];
    s_mask[1][tid]       = m0[L_SEQ + tid];
    s_mask[1][tid + 256] = m0[L_SEQ + tid + 256];
    __syncthreads();

    // ---------------- Phase 1: scores for both rows ----------------
    // Warp w owns j in [w*64,(w+1)*64). Half-warp (16 lanes x float4) computes
    // one j: load k[j] ONCE, rk for both rows, two dot products.
    const float4 qa0 = *reinterpret_cast<const float4*>(q0 + 4 * hl);
    const float4 qa1 = *reinterpret_cast<const float4*>(q0 + D_DIM + 4 * hl);

    #pragma unroll 2
    for (int jj = 0; jj < 32; ++jj) {
        const int j  = (warp << 6) + (jj << 1) + half;
        const size_t off = (size_t)j * D_DIM + 4 * hl;
        const float4 kv = *reinterpret_cast<const float4*>(krow + off);
        const float4 r0 = __ldcs(reinterpret_cast<const float4*>(rk0 + off));
        const float4 r1 = __ldcs(reinterpret_cast<const float4*>(rk0 + (size_t)L_SEQ * D_DIM + off));
        float p0 = qa0.x * (kv.x + r0.x) + qa0.y * (kv.y + r0.y)
                 + qa0.z * (kv.z + r0.z) + qa0.w * (kv.w + r0.w);
        float p1 = qa1.x * (kv.x + r1.x) + qa1.y * (kv.y + r1.y)
                 + qa1.z * (kv.z + r1.z) + qa1.w * (kv.w + r1.w);
        p0 += __shfl_xor_sync(0xffffffffu, p0, 8);
        p1 += __shfl_xor_sync(0xffffffffu, p1, 8);
        p0 += __shfl_xor_sync(0xffffffffu, p0, 4);
        p1 += __shfl_xor_sync(0xffffffffu, p1, 4);
        p0 += __shfl_xor_sync(0xffffffffu, p0, 2);
        p1 += __shfl_xor_sync(0xffffffffu, p1, 2);
        p0 += __shfl_xor_sync(0xffffffffu, p0, 1);
        p1 += __shfl_xor_sync(0xffffffffu, p1, 1);
        if (hl == 0) {
            float s0 = p0 * 0.125f;                 // 1/sqrt(64)
            float s1 = p1 * 0.125f;
            if (s_mask[0][j] == 0) s0 = -1e9f;
            if (s_mask[1][j] == 0) s1 = -1e9f;
            s_score[0][j] = s0;
            s_score[1][j] = s1;
        }
    }
    __syncthreads();

    // ---------------- Phase 2: dual softmax ----------------
    // Warps 0-3 handle row 0, warps 4-7 row 1. Each thread owns 4 contiguous scores.
    const int row = tid >> 7;
    const int t   = tid & 127;
    float4 sv = *reinterpret_cast<const float4*>(&s_score[row][4 * t]);

    float m = fmaxf(fmaxf(sv.x, sv.y), fmaxf(sv.z, sv.w));
    #pragma unroll
    for (int o = 16; o > 0; o >>= 1)
        m = fmaxf(m, __shfl_xor_sync(0xffffffffu, m, o));
    if (lane == 0) s_red[row][warp & 3] = m;
    __syncthreads();
    const float mm = fmaxf(fmaxf(s_red[row][0], s_red[row][1]),
                           fmaxf(s_red[row][2], s_red[row][3]));

    const float e0 = __expf(sv.x - mm);
    const float e1 = __expf(sv.y - mm);
    const float e2 = __expf(sv.z - mm);
    const float e3 = __expf(sv.w - mm);
    float ssum = (e0 + e1) + (e2 + e3);
    #pragma unroll
    for (int o = 16; o > 0; o >>= 1)
        ssum += __shfl_xor_sync(0xffffffffu, ssum, o);
    __syncthreads();                      // s_red reuse
    if (lane == 0) s_red[row][warp & 3] = ssum;
    __syncthreads();
    const float inv = 1.0f / ((s_red[row][0] + s_red[row][1]) +
                              (s_red[row][2] + s_red[row][3]));

    const float4 pv = make_float4(e0 * inv, e1 * inv, e2 * inv, e3 * inv);
    *reinterpret_cast<float4*>(&s_score[row][4 * t]) = pv;
    const size_t pbase = ((size_t)h * L_SEQ + i0 + row) * L_SEQ;
    *reinterpret_cast<float4*>(&out_p[pbase + 4 * t]) = pv;
    __syncthreads();

    // ---------------- Phase 3: outputs for both rows ----------------
    // 16 j-groups (warp*2 + half) x 16 lanes (float4 over d). One v[j] load
    // feeds both rows' accumulators.
    const int gid = (warp << 1) + half;
    const float* vrow = v_g  + (size_t)h * L_SEQ * D_DIM;
    const float* rv0  = rv_g + ((size_t)h * L_SEQ + i0) * L_SEQ * D_DIM;

    float4 a0 = make_float4(0.f, 0.f, 0.f, 0.f);
    float4 a1 = make_float4(0.f, 0.f, 0.f, 0.f);
    #pragma unroll 2
    for (int j = gid; j < L_SEQ; j += 16) {
        const float  pj0 = s_score[0][j];
        const float  pj1 = s_score[1][j];
        const size_t off = (size_t)j * D_DIM + 4 * hl;
        const float4 vv = *reinterpret_cast<const float4*>(vrow + off);
        const float4 r0 = __ldcs(reinterpret_cast<const float4*>(rv0 + off));
        const float4 r1 = __ldcs(reinterpret_cast<const float4*>(rv0 + (size_t)L_SEQ * D_DIM + off));
        a0.x += pj0 * (vv.x + r0.x);
        a0.y += pj0 * (vv.y + r0.y);
        a0.z += pj0 * (vv.z + r0.z);
        a0.w += pj0 * (vv.w + r0.w);
        a1.x += pj1 * (vv.x + r1.x);
        a1.y += pj1 * (vv.y + r1.y);
        a1.z += pj1 * (vv.z + r1.z);
        a1.w += pj1 * (vv.w + r1.w);
    }
    s_acc[0][gid][hl] = a0;
    s_acc[1][gid][hl] = a1;
    __syncthreads();

    if (tid < 32) {
        const int r  = tid >> 4;
        const int dq = tid & 15;
        float4 s = make_float4(0.f, 0.f, 0.f, 0.f);
        #pragma unroll
        for (int gg = 0; gg < 16; ++gg) {
            const float4 a = s_acc[r][gg][dq];
            s.x += a.x; s.y += a.y; s.z += a.z; s.w += a.w;
        }
        float4* oa = reinterpret_cast<float4*>(out_attn + ((size_t)h * L_SEQ + i0 + r) * D_DIM);
        oa[dq] = s;
    }
}

extern "C" void kernel_launch(void* const* d_in, const int* in_sizes, int n_in,
                              void* d_out, int out_size)
{
    const float* q    = (const float*)d_in[0];
    const float* k    = (const float*)d_in[1];
    const float* v    = (const float*)d_in[2];
    const float* rk   = (const float*)d_in[3];
    const float* rv   = (const float*)d_in[4];
    const int*   mask = (const int*)  d_in[5];

    float* out      = (float*)d_out;
    float* out_attn = out;                                        // [1,8,512,64]
    float* out_p    = out + (size_t)H_HEADS * L_SEQ * D_DIM;      // [1,8,512,512]

    dim3 grid(L_SEQ / 2, H_HEADS);
    rel_attn_kernel<<<grid, NTHREADS>>>(q, k, v, rk, rv, mask, out_attn, out_p);
}